// round 4
// baseline (speedup 1.0000x reference)
#include <cuda_runtime.h>
#include <cstdint>

// Problem constants (match reference_code)
#define USER_NUM  1000000
#define EMBED_DIM 64
#define BATCH     16384

// Per-CTA work split: 64 elements, half via LDG gathers (L1/LSU path),
// half via cp.async.bulk row copies (TMA engine path). The two memory
// paths have independent outstanding-transaction tracking, so their
// throughputs add (per-SM LDG miss concurrency is HW-capped at ~12
// 256B-requests; measured R2/R3 invariance proves LDG shaping is dead).
#define E_PER_CTA 64
#define LDG_E     32
#define TMA_E     32
#define TMA_BYTES (TMA_E * 2 * 256)   // 64 rows x 256B = 16384

__device__ __forceinline__ uint32_t smem_u32(const void* p) {
    return (uint32_t)__cvta_generic_to_shared(p);
}

__global__ void __launch_bounds__(256) fm_dual_path_kernel(
    const int*   __restrict__ inp,   // [BATCH, 2] int32
    const float* __restrict__ w,     // [USER_NUM + ITEM_NUM]
    const float* __restrict__ bptr,  // [1]
    const float* __restrict__ V,     // [USER_NUM + ITEM_NUM, 64]
    float*       __restrict__ out)   // [BATCH]
{
    __shared__ __align__(1024) float rows[TMA_E * 2][EMBED_DIM]; // 16 KB
    __shared__ uint64_t mbar;

    const int tid    = threadIdx.x;
    const int e_base = blockIdx.x * E_PER_CTA;
    const int grp    = tid >> 4;     // 0..15: 16-lane group id
    const int lane   = tid & 15;

    // ---- mbarrier init (count=1; tid0 arrives via expect_tx) ----
    if (tid == 0) {
        uint32_t mb = smem_u32(&mbar);
        asm volatile("mbarrier.init.shared.b64 [%0], 1;" :: "r"(mb) : "memory");
    }

    // ---- Phase A: issue everything independent as early as possible ----

    // LDG path: thread handles (elem grp, lane) and (elem 16+grp, lane).
    const int2 ia = __ldg(reinterpret_cast<const int2*>(inp) + (e_base + grp));
    const int2 ib = __ldg(reinterpret_cast<const int2*>(inp) + (e_base + 16 + grp));
    const long long ua = (long long)ia.x;
    const long long va_i = (long long)ia.y + USER_NUM;
    const long long ub = (long long)ib.x;
    const long long vb_i = (long long)ib.y + USER_NUM;

    const float4 au = __ldg(reinterpret_cast<const float4*>(V + ua   * EMBED_DIM) + lane);
    const float4 ai = __ldg(reinterpret_cast<const float4*>(V + va_i * EMBED_DIM) + lane);
    const float4 bu = __ldg(reinterpret_cast<const float4*>(V + ub   * EMBED_DIM) + lane);
    const float4 bi = __ldg(reinterpret_cast<const float4*>(V + vb_i * EMBED_DIM) + lane);

    // TMA-path index + issue prep: threads 32..63 own TMA elements.
    int2 it = make_int2(0, 0);
    if (tid >= 32 && tid < 64) {
        it = __ldg(reinterpret_cast<const int2*>(inp) + (e_base + 32 + (tid - 32)));
    }

    // w preloads for group leaders (kills the serial w-load tail):
    // leader of group g covers elems g, 16+g (LDG) and 32+g, 48+g (TMA).
    float wsum_a = 0.f, wsum_b = 0.f, wsum_c = 0.f, wsum_d = 0.f;
    int2 ic = make_int2(0, 0), id_ = make_int2(0, 0);
    if (lane == 0) {
        ic  = __ldg(reinterpret_cast<const int2*>(inp) + (e_base + 32 + grp));
        id_ = __ldg(reinterpret_cast<const int2*>(inp) + (e_base + 48 + grp));
        const float bb = __ldg(&bptr[0]);
        wsum_a = __ldg(&w[ua]) + __ldg(&w[va_i]) + bb;
        wsum_b = __ldg(&w[ub]) + __ldg(&w[vb_i]) + bb;
        wsum_c = __ldg(&w[(long long)ic.x]) + __ldg(&w[(long long)ic.y + USER_NUM]) + bb;
        wsum_d = __ldg(&w[(long long)id_.x]) + __ldg(&w[(long long)id_.y + USER_NUM]) + bb;
    }

    __syncthreads();   // mbarrier init visible before any bulk completion

    if (tid == 0) {
        uint32_t mb = smem_u32(&mbar);
        asm volatile("mbarrier.arrive.expect_tx.shared.b64 _, [%0], %1;"
                     :: "r"(mb), "r"((uint32_t)TMA_BYTES) : "memory");
    }
    if (tid >= 32 && tid < 64) {
        const int k = tid - 32;                       // 0..31, elem_local = 32+k
        const uint32_t mb = smem_u32(&mbar);
        const uint32_t du = smem_u32(&rows[2 * k][0]);
        const uint32_t di = smem_u32(&rows[2 * k + 1][0]);
        const float* su = V + (long long)it.x * EMBED_DIM;
        const float* si = V + ((long long)it.y + USER_NUM) * EMBED_DIM;
        asm volatile(
            "cp.async.bulk.shared::cluster.global.mbarrier::complete_tx::bytes [%0], [%1], 256, [%2];"
            :: "r"(du), "l"(su), "r"(mb) : "memory");
        asm volatile(
            "cp.async.bulk.shared::cluster.global.mbarrier::complete_tx::bytes [%0], [%1], 256, [%2];"
            :: "r"(di), "l"(si), "r"(mb) : "memory");
    }

    // ---- Phase B: LDG-path dots (loads already in flight) ----
    float dot_a = au.x * ai.x + au.y * ai.y + au.z * ai.z + au.w * ai.w;
    float dot_b = bu.x * bi.x + bu.y * bi.y + bu.z * bi.z + bu.w * bi.w;

    #pragma unroll
    for (int off = 8; off > 0; off >>= 1) {
        dot_a += __shfl_xor_sync(0xffffffffu, dot_a, off);
        dot_b += __shfl_xor_sync(0xffffffffu, dot_b, off);
    }
    if (lane == 0) {
        out[e_base + grp]      = wsum_a + dot_a;
        out[e_base + 16 + grp] = wsum_b + dot_b;
    }

    // ---- Phase C: wait for bulk rows, compute TMA-path dots ----
    {
        const uint32_t mb = smem_u32(&mbar);
        asm volatile(
            "{\n\t"
            ".reg .pred P;\n\t"
            "WAIT_%=:\n\t"
            "mbarrier.try_wait.parity.shared.b64 P, [%0], 0;\n\t"
            "@P bra DONE_%=;\n\t"
            "bra WAIT_%=;\n\t"
            "DONE_%=:\n\t"
            "}"
            :: "r"(mb) : "memory");
    }

    // elem 32+grp uses rows[2*grp], rows[2*grp+1]; elem 48+grp uses rows[2*(16+grp)]...
    const float4 cu = *reinterpret_cast<const float4*>(&rows[2 * grp][lane * 4]);
    const float4 ci = *reinterpret_cast<const float4*>(&rows[2 * grp + 1][lane * 4]);
    const float4 du4 = *reinterpret_cast<const float4*>(&rows[2 * (16 + grp)][lane * 4]);
    const float4 di4 = *reinterpret_cast<const float4*>(&rows[2 * (16 + grp) + 1][lane * 4]);

    float dot_c = cu.x * ci.x + cu.y * ci.y + cu.z * ci.z + cu.w * ci.w;
    float dot_d = du4.x * di4.x + du4.y * di4.y + du4.z * di4.z + du4.w * di4.w;

    #pragma unroll
    for (int off = 8; off > 0; off >>= 1) {
        dot_c += __shfl_xor_sync(0xffffffffu, dot_c, off);
        dot_d += __shfl_xor_sync(0xffffffffu, dot_d, off);
    }
    if (lane == 0) {
        out[e_base + 32 + grp] = wsum_c + dot_c;
        out[e_base + 48 + grp] = wsum_d + dot_d;
    }
}

extern "C" void kernel_launch(void* const* d_in, const int* in_sizes, int n_in,
                              void* d_out, int out_size)
{
    const int*   inp = (const int*)d_in[0];
    const float* w   = (const float*)d_in[1];
    const float* b   = (const float*)d_in[2];
    const float* V   = (const float*)d_in[3];
    float*       out = (float*)d_out;

    const int blocks = BATCH / E_PER_CTA;   // 256
    fm_dual_path_kernel<<<blocks, 256>>>(inp, w, b, V, out);
}

// round 5
// speedup vs baseline: 1.3131x; 1.3131x over previous
#include <cuda_runtime.h>
#include <cstdint>

// Problem constants (match reference_code)
#define USER_NUM  1000000
#define EMBED_DIM 64
#define BATCH     16384

// FM scoring: out[e] = w[u] + w[i] + b + dot(V[u], V[i])
// INPUT is int32 on the wire (JAX x64 disabled downgrades int64->int32).
//
// R2 structure (16 lanes/element, float4 gathers, shuffle reduce) +
// fire-and-forget prefetch.global.L2 of all gathered lines. Prefetches
// hold no L1 MSHR, so they run ahead of the MSHR-capped LDG stream and
// convert later LDG misses into L2 hits, shortening MSHR hold time.
__global__ void __launch_bounds__(256) fm_score_kernel(
    const int*   __restrict__ inp,   // [BATCH, 2] int32
    const float* __restrict__ w,     // [USER_NUM + ITEM_NUM]
    const float* __restrict__ bptr,  // [1]
    const float* __restrict__ V,     // [USER_NUM + ITEM_NUM, 64]
    float*       __restrict__ out)   // [BATCH]
{
    const int gid  = blockIdx.x * blockDim.x + threadIdx.x;
    const int elem = gid >> 4;       // 16 lanes per element
    const int lane = gid & 15;
    if (elem >= BATCH) return;

    const int2 idx = __ldg(reinterpret_cast<const int2*>(inp) + elem);
    const long long u = (long long)idx.x;
    const long long i = (long long)idx.y + USER_NUM;

    const float* up = V + u * EMBED_DIM;   // 256B row = 2 x 128B lines
    const float* ip = V + i * EMBED_DIM;

    // Fire-and-forget L2 prefetch: lanes 0,4,8,12 cover the 4 lines
    // (u+0, u+128B, i+0, i+128B). No MSHR, no register dependency.
    if ((lane & 3) == 0) {
        const float* p = (lane < 8) ? up : ip;
        p += (lane & 4) ? 32 : 0;          // +128 bytes
        asm volatile("prefetch.global.L2 [%0];" :: "l"(p));
    }

    // Gathers, back-to-back (MLP=2/thread; chip-wide depth comes from warps).
    const float4 a = __ldg(reinterpret_cast<const float4*>(up) + lane);
    const float4 c = __ldg(reinterpret_cast<const float4*>(ip) + lane);

    // Linear terms issued early (broadcast loads), not after the reduce.
    float wsum = 0.0f;
    if (lane == 0)
        wsum = __ldg(&w[u]) + __ldg(&w[i]) + __ldg(&bptr[0]);

    float dot = a.x * c.x + a.y * c.y + a.z * c.z + a.w * c.w;

    #pragma unroll
    for (int off = 8; off > 0; off >>= 1)
        dot += __shfl_xor_sync(0xffffffffu, dot, off);

    if (lane == 0)
        out[elem] = wsum + dot;
}

extern "C" void kernel_launch(void* const* d_in, const int* in_sizes, int n_in,
                              void* d_out, int out_size)
{
    const int*   inp = (const int*)d_in[0];    // INPUT int32 [BATCH,2]
    const float* w   = (const float*)d_in[1];  // w
    const float* b   = (const float*)d_in[2];  // b
    const float* V   = (const float*)d_in[3];  // V
    float*       out = (float*)d_out;          // [BATCH,1] float32

    const int threads = 256;
    const int total   = BATCH * 16;            // 16 lanes per element
    const int blocks  = (total + threads - 1) / threads;
    fm_score_kernel<<<blocks, threads>>>(inp, w, b, V, out);
}

// round 6
// speedup vs baseline: 1.3510x; 1.0288x over previous
#include <cuda_runtime.h>
#include <cstdint>

// Problem constants (match reference_code)
#define USER_NUM  1000000
#define EMBED_DIM 64
#define BATCH     16384

#define THREADS        128
#define ELEMS_PER_CTA  32
#define ROWS_PER_CTA   (ELEMS_PER_CTA * 2)        // 64 rows x 256B = 16KB
#define CHUNKS_PER_ROW 16                          // 16B chunks per 256B row
#define TOTAL_CHUNKS   (ROWS_PER_CTA * CHUNKS_PER_ROW)  // 1024
#define CHUNKS_PER_THR (TOTAL_CHUNKS / THREADS)    // 8

// FM scoring: out[e] = w[u] + w[i] + b + dot(V[u], V[i])
// INPUT is int32 on the wire.
//
// The LDG path is capped at ~14 outstanding miss-lines per SM (proven by
// occ/MLP/prefetch invariance R2-R5). cp.async.cg has no observed depth
// cap on B300 and bypasses L1: each CTA puts its whole 16KB tile in
// flight, flipping the kernel from MSHR-latency-bound to DRAM-service-bound.
__global__ void __launch_bounds__(THREADS) fm_cpasync_kernel(
    const int*   __restrict__ inp,   // [BATCH, 2] int32
    const float* __restrict__ w,     // [USER_NUM + ITEM_NUM]
    const float* __restrict__ bptr,  // [1]
    const float* __restrict__ V,     // [USER_NUM + ITEM_NUM, 64]
    float*       __restrict__ out)   // [BATCH]
{
    __shared__ __align__(16) float rows[ROWS_PER_CTA][EMBED_DIM]; // 16KB
    __shared__ int sidx[ELEMS_PER_CTA * 2];                       // 256B

    const int tid    = threadIdx.x;
    const int e_base = blockIdx.x * ELEMS_PER_CTA;

    // Stage this CTA's indices: one coalesced 256B read.
    if (tid < ELEMS_PER_CTA * 2)
        sidx[tid] = __ldg(&inp[e_base * 2 + tid]);
    __syncthreads();

    // Issue 8 x 16B cp.async.cg per thread (deep, register-free pipeline).
    #pragma unroll
    for (int k = 0; k < CHUNKS_PER_THR; k++) {
        const int c     = tid + k * THREADS;   // 0..1023
        const int r     = c >> 4;              // row 0..63
        const int chunk = c & 15;              // 16B chunk within row
        const int e     = r >> 1;
        const int side  = r & 1;
        const unsigned idx = side ? (unsigned)sidx[2 * e + 1] + USER_NUM
                                  : (unsigned)sidx[2 * e];
        const float* src = V + (size_t)idx * EMBED_DIM + chunk * 4;
        const uint32_t dst =
            (uint32_t)__cvta_generic_to_shared(&rows[r][chunk * 4]);
        asm volatile("cp.async.cg.shared.global [%0], [%1], 16;"
                     :: "r"(dst), "l"(src) : "memory");
    }
    asm volatile("cp.async.commit_group;" ::: "memory");

    // Linear terms via LDG while the bulk copy is in flight.
    // 8 groups of 16 lanes; group g's leader covers elems g, g+8, g+16, g+24.
    const int grp  = tid >> 4;
    const int lane = tid & 15;
    float wsum[4] = {0.f, 0.f, 0.f, 0.f};
    if (lane == 0) {
        const float bb = __ldg(&bptr[0]);
        #pragma unroll
        for (int q = 0; q < 4; q++) {
            const int e = grp + q * 8;
            const unsigned u = (unsigned)sidx[2 * e];
            const unsigned i = (unsigned)sidx[2 * e + 1] + USER_NUM;
            wsum[q] = __ldg(&w[u]) + __ldg(&w[i]) + bb;
        }
    }

    asm volatile("cp.async.wait_group 0;" ::: "memory");
    __syncthreads();

    // Dot products from SMEM: elem e uses rows[2e] (Vu) and rows[2e+1] (Vi).
    #pragma unroll
    for (int q = 0; q < 4; q++) {
        const int e = grp + q * 8;
        const float4 a = *reinterpret_cast<const float4*>(&rows[2 * e][lane * 4]);
        const float4 c = *reinterpret_cast<const float4*>(&rows[2 * e + 1][lane * 4]);
        float dot = a.x * c.x + a.y * c.y + a.z * c.z + a.w * c.w;
        #pragma unroll
        for (int off = 8; off > 0; off >>= 1)
            dot += __shfl_xor_sync(0xffffffffu, dot, off);
        if (lane == 0)
            out[e_base + e] = wsum[q] + dot;
    }
}

extern "C" void kernel_launch(void* const* d_in, const int* in_sizes, int n_in,
                              void* d_out, int out_size)
{
    const int*   inp = (const int*)d_in[0];    // INPUT int32 [BATCH,2]
    const float* w   = (const float*)d_in[1];  // w
    const float* b   = (const float*)d_in[2];  // b
    const float* V   = (const float*)d_in[3];  // V
    float*       out = (float*)d_out;          // [BATCH,1] float32

    const int blocks = BATCH / ELEMS_PER_CTA;  // 512
    fm_cpasync_kernel<<<blocks, THREADS>>>(inp, w, b, V, out);
}